// round 17
// baseline (speedup 1.0000x reference)
#include <cuda_runtime.h>
#include <math.h>
#include <stdint.h>

#define TOTAL   5120
#define DIMM    1024
#define NH      16
#define HDD     64
#define NB      4
#define MAXLEN  2048
#define NQKV    3072

// Scratch (device globals: no allocation allowed)
__device__ float g_qkv[(size_t)TOTAL * NQKV];    // q|k|v (tf32 values)
__device__ float g_attn[(size_t)TOTAL * DIMM];   // attention out (tf32 values)
__device__ float g_a [(size_t)TOTAL * DIMM];     // hs rounded to tf32
__device__ float g_w1[(size_t)NQKV * DIMM];      // Wqkv rounded to tf32
__device__ float g_w2[(size_t)DIMM * DIMM];      // Wo rounded to tf32

extern __shared__ __align__(1024) uint8_t dynraw[];

__device__ __forceinline__ unsigned tf32r(float x) {
    unsigned u;
    asm("cvt.rna.tf32.f32 %0, %1;" : "=r"(u) : "f"(x));
    return u;
}
__device__ __forceinline__ float tf32rf(float x) {
    return __uint_as_float(tf32r(x));
}
__device__ __forceinline__ float ex2f(float x) {
    float r;
    asm("ex2.approx.f32 %0, %1;" : "=f"(r) : "f"(x));
    return r;
}

#define MMA_TF32(acc, a0,a1,a2,a3, b0,b1)                                     \
    asm volatile("mma.sync.aligned.m16n8k8.row.col.f32.tf32.tf32.f32 "        \
                 "{%0,%1,%2,%3}, {%4,%5,%6,%7}, {%8,%9}, {%0,%1,%2,%3};"      \
                 : "+f"((acc)[0]), "+f"((acc)[1]), "+f"((acc)[2]), "+f"((acc)[3]) \
                 : "r"(a0), "r"(a1), "r"(a2), "r"(a3), "r"(b0), "r"(b1))

// ---------------------------------------------------------------------------
// Elementwise round-to-tf32 copy (vectorized).
// ---------------------------------------------------------------------------
__global__ void __launch_bounds__(256) cvt_tf32(const float* __restrict__ src,
                                                float* __restrict__ dst, int n4)
{
    int i = blockIdx.x * 256 + threadIdx.x;
    if (i >= n4) return;
    float4 v = ((const float4*)src)[i];
    v.x = tf32rf(v.x); v.y = tf32rf(v.y);
    v.z = tf32rf(v.z); v.w = tf32rf(v.w);
    ((float4*)dst)[i] = v;
}

// ===========================================================================
// GEMM: 128x128 CTA tile, 4 warps (2x2), warp tile 64x64, 3-STAGE cp.async
// ring (wait_group 1: stage i+2 issued two compute blocks ahead). 96KB smem,
// 128 threads, occ 2. Inputs pre-rounded tf32.
// ===========================================================================
__global__ void __launch_bounds__(128, 2) mma_gemm_nt(
    const float* __restrict__ A, const float* __restrict__ Bw,
    float* __restrict__ C, int M, int N, int K, int round_out)
{
    const int tid  = threadIdx.x;
    const int lane = tid & 31, w = tid >> 5;     // 4 warps
    const int g = lane >> 2, t = lane & 3;
    const int wm = w >> 1, wn = w & 1;           // 2 x 2 warp grid
    const int bm = blockIdx.y * 128, bn = blockIdx.x * 128;

    float acc[4][8][4] = {};

    const unsigned sbase = (unsigned)__cvta_generic_to_shared(dynraw);
    const int T = K >> 5;

#define GEMM_STAGE(j)                                                         \
    {                                                                         \
        if ((j) < T) {                                                        \
            unsigned sa = sbase + (unsigned)((j) % 3) * 32768u;               \
            int k0 = (j) << 5;                                                \
            _Pragma("unroll")                                                 \
            for (int it = 0; it < 8; it++) {                                  \
                int id = tid + 128 * it;                                      \
                int row = id >> 3, c = id & 7;                                \
                unsigned off = (unsigned)(row * 32 + ((c ^ (row & 7)) << 2)) * 4; \
                asm volatile("cp.async.ca.shared.global [%0],[%1],16;\n"      \
                             :: "r"(sa + off), "l"(&A [(size_t)(bm + row) * K + k0 + c * 4])); \
                asm volatile("cp.async.ca.shared.global [%0],[%1],16;\n"      \
                             :: "r"(sa + 16384u + off), "l"(&Bw[(size_t)(bn + row) * K + k0 + c * 4])); \
            }                                                                 \
        }                                                                     \
        asm volatile("cp.async.commit_group;\n");                             \
    }

    GEMM_STAGE(0);
    GEMM_STAGE(1);

    for (int i = 0; i < T; i++) {
        asm volatile("cp.async.wait_group 1;\n");   // tile i complete
        __syncthreads();                            // all warps past compute(i-1)
        GEMM_STAGE(i + 2);                          // overwrites buffer (i-1)%3

        const float* Ab = (const float*)(dynraw + (i % 3) * 32768);
        const float* Bb = (const float*)(dynraw + (i % 3) * 32768 + 16384);
#pragma unroll
        for (int o = 0; o < 4; o++) {
            const int c0 = ((2 * o) ^ g) << 2, c1 = ((2 * o + 1) ^ g) << 2;
            unsigned a[4][4], b[8][2];
#pragma unroll
            for (int mt = 0; mt < 4; mt++) {
                int r0 = wm * 64 + mt * 16 + g;
                a[mt][0] = __float_as_uint(Ab[ r0      * 32 + c0 + t]);
                a[mt][2] = __float_as_uint(Ab[ r0      * 32 + c1 + t]);
                a[mt][1] = __float_as_uint(Ab[(r0 + 8) * 32 + c0 + t]);
                a[mt][3] = __float_as_uint(Ab[(r0 + 8) * 32 + c1 + t]);
            }
#pragma unroll
            for (int nt = 0; nt < 8; nt++) {
                int rb = wn * 64 + nt * 8 + g;
                b[nt][0] = __float_as_uint(Bb[rb * 32 + c0 + t]);
                b[nt][1] = __float_as_uint(Bb[rb * 32 + c1 + t]);
            }
#pragma unroll
            for (int mt = 0; mt < 4; mt++)
#pragma unroll
                for (int nt = 0; nt < 8; nt++)
                    MMA_TF32(acc[mt][nt], a[mt][0], a[mt][1], a[mt][2], a[mt][3],
                             b[nt][0], b[nt][1]);
        }
    }

#pragma unroll
    for (int mt = 0; mt < 4; mt++) {
        int r = bm + wm * 64 + mt * 16 + g;
#pragma unroll
        for (int nt = 0; nt < 8; nt++) {
            int cn = bn + wn * 64 + nt * 8 + 2 * t;
            float v0 = acc[mt][nt][0], v1 = acc[mt][nt][1];
            float v2 = acc[mt][nt][2], v3 = acc[mt][nt][3];
            if (round_out) {
                v0 = tf32rf(v0); v1 = tf32rf(v1); v2 = tf32rf(v2); v3 = tf32rf(v3);
            }
            *(float2*)&C[(size_t)r * N + cn]       = make_float2(v0, v1);
            *(float2*)&C[(size_t)(r + 8) * N + cn] = make_float2(v2, v3);
        }
    }
}

// ---------------------------------------------------------------------------
// RoPE in-place on q,k sections of g_qkv; outputs rounded to tf32.
// ---------------------------------------------------------------------------
__global__ void __launch_bounds__(256) rope_kernel(const int* __restrict__ cu)
{
    int tt = blockIdx.x * 256 + threadIdx.x;
    int j  = tt & 31;
    int hh = (tt >> 5) & 15;
    int s  = (tt >> 9) & 1;
    int r  = tt >> 10;
    if (r >= TOTAL) return;

    int b = 0;
#pragma unroll
    for (int i = 1; i < NB; i++) if (r >= cu[i]) b = i;
    int pos = r - cu[b];

    float inv = exp2f(-(float)j * (13.287712379549449f / 32.0f));
    float fr  = (float)pos * inv;
    float c, sn;
    sincosf(fr, &sn, &c);

    float* base = g_qkv + (size_t)r * NQKV + s * DIMM + hh * HDD;
    float x1 = base[j], x2 = base[j + 32];
    base[j]      = tf32rf(x1 * c - x2 * sn);
    base[j + 32] = tf32rf(x2 * c + x1 * sn);
}

// ---------------------------------------------------------------------------
// Tensor-core flash attention (tf32, mma.sync), DOUBLE-BUFFERED K and V:
// one wait + two barriers per k-tile (was 2+3); K staged 1.5 iters ahead,
// V one iter ahead. Q fragments register-resident (staged via Ps). 4 warps,
// V stride-72 (conflict-free), base-2 softmax. 100KB smem, occ 2.
// Smem: K 2x16KB @0, V 2x18KB @8192f, Ps 32KB @17408f.
// ---------------------------------------------------------------------------
__global__ void __launch_bounds__(128, 2) attn_kernel(const int* __restrict__ cu)
{
    float* KsB = (float*)dynraw;               // 2 x 64*64 swizzled
    float* VsB = (float*)dynraw + 8192;        // 2 x 64*72 stride-72
    float* Ps  = (float*)dynraw + 17408;       // 128*64 swizzled

    const int tid  = threadIdx.x;
    const int lane = tid & 31, w = tid >> 5;   // 4 warps
    const int g = lane >> 2, t = lane & 3;
    const int h  = blockIdx.y;
    const int qt = blockIdx.x * 128;

    const unsigned sK = (unsigned)__cvta_generic_to_shared(KsB);
    const unsigned sV = (unsigned)__cvta_generic_to_shared(VsB);

    int b = 0;
#pragma unroll
    for (int i = 1; i < NB; i++) if (qt >= cu[i]) b = i;
    const int base = cu[b];
    const int L    = cu[b + 1] - base;
    const int nkt  = L >> 6;

#define STAGE_K(j)                                                            \
    {                                                                         \
        if ((j) < nkt) {                                                      \
            const size_t kr0 = (size_t)(base + (j) * 64);                     \
            unsigned kb = sK + (unsigned)((j) & 1) * 16384u;                  \
            _Pragma("unroll")                                                 \
            for (int it = 0; it < 8; it++) {                                  \
                int id = tid + 128 * it;                                      \
                int row = id >> 4, c = id & 15;                               \
                unsigned off = (unsigned)(row * 64 + ((c ^ (row & 7)) << 2)) * 4; \
                asm volatile("cp.async.ca.shared.global [%0],[%1],16;\n"      \
                    :: "r"(kb + off),                                         \
                       "l"(&g_qkv[(kr0 + row) * NQKV + h * HDD + c * 4 + DIMM])); \
            }                                                                 \
        }                                                                     \
        asm volatile("cp.async.commit_group;\n");                             \
    }
#define STAGE_V(j)                                                            \
    {                                                                         \
        if ((j) < nkt) {                                                      \
            const size_t kr0 = (size_t)(base + (j) * 64);                     \
            unsigned vb = sV + (unsigned)((j) & 1) * 18432u;                  \
            _Pragma("unroll")                                                 \
            for (int it = 0; it < 8; it++) {                                  \
                int id = tid + 128 * it;                                      \
                int row = id >> 4, c = id & 15;                               \
                unsigned off = (unsigned)(row * 72 + c * 4) * 4;              \
                asm volatile("cp.async.ca.shared.global [%0],[%1],16;\n"      \
                    :: "r"(vb + off),                                         \
                       "l"(&g_qkv[(kr0 + row) * NQKV + h * HDD + c * 4 + 2 * DIMM])); \
            }                                                                 \
        }                                                                     \
        asm volatile("cp.async.commit_group;\n");                             \
    }

    // prologue: commit K0, V0, K1 (nkt >= 8 always)
    STAGE_K(0);
    STAGE_V(0);
    STAGE_K(1);

    // stage Q through Ps (scaled by (1/8)*log2(e), tf32-rounded)
    const float QSCALE = 0.18033688011112042f;
#pragma unroll
    for (int it = 0; it < 16; it++) {
        int id = tid + 128 * it;
        int row = id >> 4, c = id & 15;
        float4 v = *(const float4*)&g_qkv[(size_t)(qt + row) * NQKV + h * HDD + c * 4];
        float* d = &Ps[row * 64 + ((c ^ (row & 7)) << 2)];
        d[0] = tf32rf(v.x * QSCALE); d[1] = tf32rf(v.y * QSCALE);
        d[2] = tf32rf(v.z * QSCALE); d[3] = tf32rf(v.w * QSCALE);
    }
    __syncthreads();

    // Q fragments -> registers (Ps later overwritten only by own-warp P rows)
    const int rw0 = w * 32;
    unsigned qf[8][2][4];
#pragma unroll
    for (int o = 0; o < 8; o++) {
        const int c0 = ((2 * o) ^ g) << 2, c1 = ((2 * o + 1) ^ g) << 2;
#pragma unroll
        for (int mt = 0; mt < 2; mt++) {
            int r0 = rw0 + mt * 16 + g;
            qf[o][mt][0] = __float_as_uint(Ps[ r0      * 64 + c0 + t]);
            qf[o][mt][2] = __float_as_uint(Ps[ r0      * 64 + c1 + t]);
            qf[o][mt][1] = __float_as_uint(Ps[(r0 + 8) * 64 + c0 + t]);
            qf[o][mt][3] = __float_as_uint(Ps[(r0 + 8) * 64 + c1 + t]);
        }
    }

    float m_[2][2], l_[2][2];
#pragma unroll
    for (int mt = 0; mt < 2; mt++) {
        m_[mt][0] = -1e30f; m_[mt][1] = -1e30f;
        l_[mt][0] = 0.f;    l_[mt][1] = 0.f;
    }
    float o_[2][8][4] = {};

    for (int kt = 0; kt < nkt; kt++) {
        // newest pending group is K(kt+1): wait_group 1 => K(kt),V(kt) done
        asm volatile("cp.async.wait_group 1;\n");
        __syncthreads();          // data visible; all warps past PV(kt-1)

        STAGE_V(kt + 1);          // into V[(kt+1)&1] (readers done: barrier)

        const float* Ks = KsB + (kt & 1) * 4096;
        const float* Vs = VsB + (kt & 1) * 4608;

        // ---- S = Q K^T (Q from registers) ----
        float s[2][8][4] = {};
#pragma unroll
        for (int o = 0; o < 8; o++) {
            const int c0 = ((2 * o) ^ g) << 2, c1 = ((2 * o + 1) ^ g) << 2;
#pragma unroll
            for (int j = 0; j < 8; j++) {
                int rb = j * 8 + g;
                unsigned b0 = __float_as_uint(Ks[rb * 64 + c0 + t]);
                unsigned b1 = __float_as_uint(Ks[rb * 64 + c1 + t]);
#pragma unroll
                for (int mt = 0; mt < 2; mt++)
                    MMA_TF32(s[mt][j], qf[o][mt][0], qf[o][mt][1],
                             qf[o][mt][2], qf[o][mt][3], b0, b1);
            }
        }

        // ---- online softmax (base 2), two m-tiles ----
#pragma unroll
        for (int mt = 0; mt < 2; mt++) {
            float rm0 = -1e30f, rm1 = -1e30f;
#pragma unroll
            for (int j = 0; j < 8; j++) {
                rm0 = fmaxf(rm0, fmaxf(s[mt][j][0], s[mt][j][1]));
                rm1 = fmaxf(rm1, fmaxf(s[mt][j][2], s[mt][j][3]));
            }
#pragma unroll
            for (int off = 1; off < 4; off <<= 1) {
                rm0 = fmaxf(rm0, __shfl_xor_sync(0xffffffffu, rm0, off));
                rm1 = fmaxf(rm1, __shfl_xor_sync(0xffffffffu, rm1, off));
            }
            float mn0 = fmaxf(m_[mt][0], rm0), mn1 = fmaxf(m_[mt][1], rm1);
            float f0 = ex2f(m_[mt][0] - mn0), f1 = ex2f(m_[mt][1] - mn1);
            float rs0 = 0.f, rs1 = 0.f;
#pragma unroll
            for (int j = 0; j < 8; j++) {
                s[mt][j][0] = ex2f(s[mt][j][0] - mn0); rs0 += s[mt][j][0];
                s[mt][j][1] = ex2f(s[mt][j][1] - mn0); rs0 += s[mt][j][1];
                s[mt][j][2] = ex2f(s[mt][j][2] - mn1); rs1 += s[mt][j][2];
                s[mt][j][3] = ex2f(s[mt][j][3] - mn1); rs1 += s[mt][j][3];
            }
#pragma unroll
            for (int off = 1; off < 4; off <<= 1) {
                rs0 += __shfl_xor_sync(0xffffffffu, rs0, off);
                rs1 += __shfl_xor_sync(0xffffffffu, rs1, off);
            }
            l_[mt][0] = l_[mt][0] * f0 + rs0;  m_[mt][0] = mn0;
            l_[mt][1] = l_[mt][1] * f1 + rs1;  m_[mt][1] = mn1;
#pragma unroll
            for (int j = 0; j < 8; j++) {
                o_[mt][j][0] *= f0; o_[mt][j][1] *= f0;
                o_[mt][j][2] *= f1; o_[mt][j][3] *= f1;
            }

            // ---- P -> warp-local swizzled smem (own rows of Ps) ----
#pragma unroll
            for (int j = 0; j < 8; j++) {
                int ch = 2 * j + (t >> 1);
                int wd = 2 * (t & 1);
                int r0 = rw0 + mt * 16 + g;
                float* p0 = &Ps[ r0      * 64 + ((ch ^ g) << 2) + wd];
                p0[0] = tf32rf(s[mt][j][0]);
                p0[1] = tf32rf(s[mt][j][1]);
                float* p1 = &Ps[(r0 + 8) * 64 + ((ch ^ g) << 2) + wd];
                p1[0] = tf32rf(s[mt][j][2]);
                p1[1] = tf32rf(s[mt][j][3]);
            }
        }
        __syncwarp();

        // ---- O += P V  (V(kt) already waited at top) ----
#pragma unroll
        for (int o = 0; o < 8; o++) {
            const int c0 = ((2 * o) ^ g) << 2, c1 = ((2 * o + 1) ^ g) << 2;
            unsigned a[2][4];
#pragma unroll
            for (int mt = 0; mt < 2; mt++) {
                int r0 = rw0 + mt * 16 + g;
                a[mt][0] = __float_as_uint(Ps[ r0      * 64 + c0 + t]);
                a[mt][2] = __float_as_uint(Ps[ r0      * 64 + c1 + t]);
                a[mt][1] = __float_as_uint(Ps[(r0 + 8) * 64 + c0 + t]);
                a[mt][3] = __float_as_uint(Ps[(r0 + 8) * 64 + c1 + t]);
            }
            const int kr  = 8 * o + t;
            const int kr2 = kr + 4;
#pragma unroll
            for (int j = 0; j < 8; j++) {
                unsigned b0 = __float_as_uint(Vs[kr  * 72 + j * 8 + g]);
                unsigned b1 = __float_as_uint(Vs[kr2 * 72 + j * 8 + g]);
#pragma unroll
                for (int mt = 0; mt < 2; mt++)
                    MMA_TF32(o_[mt][j], a[mt][0], a[mt][1], a[mt][2], a[mt][3], b0, b1);
            }
        }

        __syncthreads();          // all warps done QK^T(kt) & PV(kt)
        STAGE_K(kt + 2);          // into K[kt&1] (readers done: barrier)
    }

    // epilogue (base 2): fold padded keys, normalize, store tf32-rounded
    const float npad = (float)(MAXLEN - L);
#pragma unroll
    for (int mt = 0; mt < 2; mt++) {
        float mf0 = (npad > 0.f) ? fmaxf(m_[mt][0], 0.f) : m_[mt][0];
        float mf1 = (npad > 0.f) ? fmaxf(m_[mt][1], 0.f) : m_[mt][1];
        float sc0 = ex2f(m_[mt][0] - mf0), sc1 = ex2f(m_[mt][1] - mf1);
        float w0 = sc0 / (l_[mt][0] * sc0 + npad * ex2f(-mf0));
        float w1 = sc1 / (l_[mt][1] * sc1 + npad * ex2f(-mf1));

        const int row0 = qt + rw0 + mt * 16 + g, row1 = row0 + 8;
#pragma unroll
        for (int j = 0; j < 8; j++) {
            int cn = h * HDD + j * 8 + 2 * t;
            *(float2*)&g_attn[(size_t)row0 * DIMM + cn] = make_float2(
                tf32rf(o_[mt][j][0] * w0), tf32rf(o_[mt][j][1] * w0));
            *(float2*)&g_attn[(size_t)row1 * DIMM + cn] = make_float2(
                tf32rf(o_[mt][j][2] * w1), tf32rf(o_[mt][j][3] * w1));
        }
    }
}

// ---------------------------------------------------------------------------
extern "C" void kernel_launch(void* const* d_in, const int* in_sizes, int n_in,
                              void* d_out, int out_size)
{
    const float* hs   = (const float*)d_in[0];
    const float* wqkv = (const float*)d_in[1];
    const float* wo   = (const float*)d_in[2];
    const int*   cu   = (const int*)  d_in[3];
    float* out = (float*)d_out;

    float *qkv_p, *attn_p, *a_p, *w1_p, *w2_p;
    cudaGetSymbolAddress((void**)&qkv_p,  g_qkv);
    cudaGetSymbolAddress((void**)&attn_p, g_attn);
    cudaGetSymbolAddress((void**)&a_p,    g_a);
    cudaGetSymbolAddress((void**)&w1_p,   g_w1);
    cudaGetSymbolAddress((void**)&w2_p,   g_w2);

    const int mma_smem  = 3 * 32768;   // 96 KB
    const int attn_smem = 102400;      // K 32K + V 36K + P 32K + pad
    cudaFuncSetAttribute(mma_gemm_nt, cudaFuncAttributeMaxDynamicSharedMemorySize, mma_smem);
    cudaFuncSetAttribute(attn_kernel, cudaFuncAttributeMaxDynamicSharedMemorySize, attn_smem);

    // 0) pre-round inputs/weights to tf32 (rna)
    cvt_tf32<<<(TOTAL * DIMM / 4 + 255) / 256, 256>>>(hs,   a_p,  TOTAL * DIMM / 4);
    cvt_tf32<<<(NQKV * DIMM / 4 + 255) / 256, 256>>>(wqkv, w1_p, NQKV * DIMM / 4);
    cvt_tf32<<<(DIMM * DIMM / 4 + 255) / 256, 256>>>(wo,   w2_p, DIMM * DIMM / 4);

    // 1) QKV projection (3-stage ring)
    mma_gemm_nt<<<dim3(NQKV / 128, TOTAL / 128), 128, mma_smem>>>(
        a_p, w1_p, qkv_p, TOTAL, NQKV, DIMM, 1);
    // 2) RoPE (rounds q,k to tf32)
    rope_kernel<<<(TOTAL * 2 * NH * 32) / 256, 256>>>(cu);
    // 3) attention (double-buffered K/V, register-resident Q)
    attn_kernel<<<dim3(TOTAL / 128, NH), 128, attn_smem>>>(cu);
    // 4) output projection (3-stage ring)
    mma_gemm_nt<<<dim3(DIMM / 128, TOTAL / 128), 128, mma_smem>>>(
        attn_p, w2_p, out, TOTAL, DIMM, DIMM, 0);
}